// round 1
// baseline (speedup 1.0000x reference)
#include <cuda_runtime.h>
#include <cuda_bf16.h>

// Problem: x[8192, 256] fp32.
//   x_hat = row-normalize(x)
//   s_ij  = x_hat_i . x_hat_j
//   loss_i = 1/sqrt(max(2 - 2*max_{j!=i} s_ij, 1e-30))   (diag term 0.1 can never win)
//   out = mean_i loss_i
//
// Fused symmetric GEMM + row-max. S never materialized.

#define N 8192
#define D 256
#define BM 128
#define BN 128
#define BK 8
#define NTHREADS 256

// Scratch (static __device__ arrays — no allocation).
__device__ float    g_xn[N * D];     // normalized rows
__device__ unsigned g_rmax[N];       // encoded running row-max of s_ij (j != i)

// Monotone order-preserving float<->uint encoding (for atomicMax over signed floats).
__device__ __forceinline__ unsigned encf(float f) {
    unsigned u = __float_as_uint(f);
    return (u & 0x80000000u) ? ~u : (u | 0x80000000u);
}
__device__ __forceinline__ float decf(unsigned u) {
    return (u & 0x80000000u) ? __uint_as_float(u & 0x7fffffffu) : __uint_as_float(~u);
}

// ---------------------------------------------------------------------------
// Kernel 1: row L2-normalize (one warp per row) + init g_rmax.
// ---------------------------------------------------------------------------
__global__ void k_normalize(const float* __restrict__ x) {
    int gtid = blockIdx.x * blockDim.x + threadIdx.x;
    int warp = gtid >> 5;
    int lane = threadIdx.x & 31;

    if (warp < N) {
        const float4* xr = reinterpret_cast<const float4*>(x + (size_t)warp * D);
        float4 v0 = xr[lane];
        float4 v1 = xr[lane + 32];
        float ss = v0.x * v0.x + v0.y * v0.y + v0.z * v0.z + v0.w * v0.w
                 + v1.x * v1.x + v1.y * v1.y + v1.z * v1.z + v1.w * v1.w;
        #pragma unroll
        for (int off = 16; off; off >>= 1)
            ss += __shfl_xor_sync(0xFFFFFFFFu, ss, off);
        float inv = 1.0f / sqrtf(ss);
        float4* xo = reinterpret_cast<float4*>(g_xn + (size_t)warp * D);
        v0.x *= inv; v0.y *= inv; v0.z *= inv; v0.w *= inv;
        v1.x *= inv; v1.y *= inv; v1.z *= inv; v1.w *= inv;
        xo[lane]      = v0;
        xo[lane + 32] = v1;
    }
    if (gtid < N) g_rmax[gtid] = encf(-2.0f);
}

// ---------------------------------------------------------------------------
// Kernel 2: fused 128x128x256 tile GEMM (S = Xn Xn^T) + row/col max epilogue.
// Only upper-triangular tile pairs (bi <= bj) are computed; symmetry updates
// both row-i maxes and row-j maxes.
// ---------------------------------------------------------------------------
__global__ __launch_bounds__(NTHREADS, 2)
void k_gemm_max() {
    const int bj = blockIdx.x;
    const int bi = blockIdx.y;
    if (bi > bj) return;

    __shared__ float As[BK][BM];
    __shared__ float Bs[BK][BN];
    __shared__ unsigned red[BM];

    const int tid = threadIdx.x;
    const int tx  = tid & 15;    // 0..15  -> col micro-tile
    const int ty  = tid >> 4;    // 0..15  -> row micro-tile

    // loading: each thread fetches one float4 from A-tile and one from B-tile
    const int lrow  = tid >> 1;          // 0..127
    const int lcol4 = (tid & 1) << 2;    // 0 or 4

    const float* A = g_xn + (size_t)(bi * BM + lrow) * D + lcol4;
    const float* B = g_xn + (size_t)(bj * BN + lrow) * D + lcol4;

    float acc[8][8];
    #pragma unroll
    for (int r = 0; r < 8; r++)
        #pragma unroll
        for (int c = 0; c < 8; c++) acc[r][c] = 0.0f;

    for (int k0 = 0; k0 < D; k0 += BK) {
        float4 av = *reinterpret_cast<const float4*>(A + k0);
        float4 bv = *reinterpret_cast<const float4*>(B + k0);
        __syncthreads();
        As[lcol4 + 0][lrow] = av.x;
        As[lcol4 + 1][lrow] = av.y;
        As[lcol4 + 2][lrow] = av.z;
        As[lcol4 + 3][lrow] = av.w;
        Bs[lcol4 + 0][lrow] = bv.x;
        Bs[lcol4 + 1][lrow] = bv.y;
        Bs[lcol4 + 2][lrow] = bv.z;
        Bs[lcol4 + 3][lrow] = bv.w;
        __syncthreads();

        #pragma unroll
        for (int kk = 0; kk < BK; kk++) {
            float af[8], bf[8];
            #pragma unroll
            for (int r = 0; r < 8; r++) af[r] = As[kk][ty * 8 + r];
            #pragma unroll
            for (int c = 0; c < 8; c++) bf[c] = Bs[kk][tx * 8 + c];
            #pragma unroll
            for (int r = 0; r < 8; r++)
                #pragma unroll
                for (int c = 0; c < 8; c++)
                    acc[r][c] = fmaf(af[r], bf[c], acc[r][c]);
        }
    }

    // ---- epilogue: row maxes for rows of tile bi ----
    if (tid < BM) red[tid] = encf(-2.0f);
    __syncthreads();
    #pragma unroll
    for (int r = 0; r < 8; r++) {
        const int gi = bi * BM + ty * 8 + r;
        float m = -2.0f;
        #pragma unroll
        for (int c = 0; c < 8; c++) {
            const int gj = bj * BN + tx * 8 + c;
            float v = (gi == gj) ? -2.0f : acc[r][c];   // exclude diagonal
            m = fmaxf(m, v);
        }
        atomicMax(&red[ty * 8 + r], encf(m));
    }
    __syncthreads();
    if (tid < BM) atomicMax(&g_rmax[bi * BM + tid], red[tid]);

    // ---- symmetry: column maxes update rows of tile bj ----
    if (bi != bj) {
        __syncthreads();
        if (tid < BM) red[tid] = encf(-2.0f);
        __syncthreads();
        #pragma unroll
        for (int c = 0; c < 8; c++) {
            float m = -2.0f;
            #pragma unroll
            for (int r = 0; r < 8; r++) m = fmaxf(m, acc[r][c]);
            atomicMax(&red[tx * 8 + c], encf(m));
        }
        __syncthreads();
        if (tid < BM) atomicMax(&g_rmax[bj * BN + tid], red[tid]);
    }
}

// ---------------------------------------------------------------------------
// Kernel 3: loss_i = 1/sqrt(max(2-2*smax_i, 1e-30)); out = mean_i loss_i.
// Deterministic fixed-order reduction.
// ---------------------------------------------------------------------------
__global__ void k_finalize(float* __restrict__ out) {
    __shared__ float sred[256];
    const int tid = threadIdx.x;
    float s = 0.0f;
    for (int i = tid; i < N; i += 256) {
        float smax = decf(g_rmax[i]);
        float d2 = fmaxf(2.0f - 2.0f * smax, 1e-30f);
        float li = fmaxf(0.1f, 1.0f / sqrtf(d2));
        s += li;
    }
    sred[tid] = s;
    __syncthreads();
    #pragma unroll
    for (int off = 128; off; off >>= 1) {
        if (tid < off) sred[tid] += sred[tid + off];
        __syncthreads();
    }
    if (tid == 0) out[0] = sred[0] / (float)N;
}

extern "C" void kernel_launch(void* const* d_in, const int* in_sizes, int n_in,
                              void* d_out, int out_size) {
    const float* x = (const float*)d_in[0];
    float* out = (float*)d_out;

    k_normalize<<<(N * 32) / 256, 256>>>(x);

    dim3 grid(N / BN, N / BM);
    k_gemm_max<<<grid, NTHREADS>>>();

    k_finalize<<<1, 256>>>(out);
}

// round 3
// speedup vs baseline: 4.4230x; 4.4230x over previous
#include <cuda_runtime.h>
#include <cstdint>

// x[8192,256] fp32 -> loss = mean_i 1/sqrt(max(2 - 2*max_{j!=i} s_ij, 1e-30))
// s = Xn Xn^T via mma.sync tf32 (base-ISA tensor path; tcgen05 is not
// assemblable under this harness's sm_103 target). Row-max fused in registers.

#define N 8192
#define D 256
#define BM 128
#define BN 128
#define BK 32
#define NTH 256
#define NSTAGE (D / BK)          // 8
#define STAGE_BYTES 32768        // A 16KB + B 16KB
#define SMEM_DYN (2 * STAGE_BYTES)

__device__ float    g_xn[N * D];   // tf32-rounded normalized rows
__device__ unsigned g_rmax[N];

__device__ __forceinline__ unsigned encf(float f) {
    unsigned u = __float_as_uint(f);
    return (u & 0x80000000u) ? ~u : (u | 0x80000000u);
}
__device__ __forceinline__ float decf(unsigned u) {
    return (u & 0x80000000u) ? __uint_as_float(u & 0x7fffffffu) : __uint_as_float(~u);
}

__device__ __forceinline__ uint32_t smem_u32(const void* p) {
    uint32_t a;
    asm("{ .reg .u64 t; cvta.to.shared.u64 t, %1; cvt.u32.u64 %0, t; }" : "=r"(a) : "l"(p));
    return a;
}
__device__ __forceinline__ uint32_t swz(uint32_t off) { return off ^ ((off >> 3) & 0x70); }

__device__ __forceinline__ void cp16(uint32_t dst, const void* src) {
    asm volatile("cp.async.cg.shared.global [%0], [%1], 16;" :: "r"(dst), "l"(src) : "memory");
}
#define CP_COMMIT()  asm volatile("cp.async.commit_group;" ::: "memory")
#define CP_WAIT(n)   asm volatile("cp.async.wait_group %0;" :: "n"(n) : "memory")

#define LDSM_X4(R0, R1, R2, R3, ADDR) \
    asm volatile("ldmatrix.sync.aligned.m8n8.x4.shared.b16 {%0,%1,%2,%3}, [%4];" \
        : "=r"(R0), "=r"(R1), "=r"(R2), "=r"(R3) : "r"(ADDR))

#define MMA_TF32(d, a, b) \
    asm volatile("mma.sync.aligned.m16n8k8.row.col.f32.tf32.tf32.f32 " \
        "{%0,%1,%2,%3}, {%4,%5,%6,%7}, {%8,%9}, {%0,%1,%2,%3};" \
        : "+f"((d)[0]), "+f"((d)[1]), "+f"((d)[2]), "+f"((d)[3]) \
        : "r"((a)[0]), "r"((a)[1]), "r"((a)[2]), "r"((a)[3]), \
          "r"((b)[0]), "r"((b)[1]))

// ---------------------------------------------------------------------------
// Kernel 1: row L2-normalize, round to tf32, init g_rmax.
// ---------------------------------------------------------------------------
__global__ void k_normalize(const float* __restrict__ x) {
    int gtid = blockIdx.x * blockDim.x + threadIdx.x;
    int row = gtid >> 5;
    int lane = threadIdx.x & 31;
    if (row < N) {
        const float4* xr = reinterpret_cast<const float4*>(x + (size_t)row * D);
        float4 v0 = xr[lane], v1 = xr[lane + 32];
        float ss = v0.x * v0.x + v0.y * v0.y + v0.z * v0.z + v0.w * v0.w +
                   v1.x * v1.x + v1.y * v1.y + v1.z * v1.z + v1.w * v1.w;
        #pragma unroll
        for (int o = 16; o; o >>= 1) ss += __shfl_xor_sync(0xFFFFFFFFu, ss, o);
        float inv = rsqrtf(ss);
        float f[8] = {v0.x, v0.y, v0.z, v0.w, v1.x, v1.y, v1.z, v1.w};
        #pragma unroll
        for (int i = 0; i < 8; i++) {
            float s = f[i] * inv;
            asm("cvt.rna.tf32.f32 %0, %1;" : "=f"(s) : "f"(s));
            f[i] = s;
        }
        float4* xo = reinterpret_cast<float4*>(g_xn + (size_t)row * D);
        xo[lane]      = make_float4(f[0], f[1], f[2], f[3]);
        xo[lane + 32] = make_float4(f[4], f[5], f[6], f[7]);
    }
    if (gtid < N) g_rmax[gtid] = encf(-2.0f);
}

// ---------------------------------------------------------------------------
// Kernel 2: 128x128 tile of S via mma.sync tf32, fused row/col max.
// ---------------------------------------------------------------------------
__global__ __launch_bounds__(NTH, 2)
void k_gemm_max() {
    const int nb = blockIdx.x;       // col block
    const int mb = blockIdx.y;       // row block
    if (mb > nb) return;             // triangular

    extern __shared__ char dsm[];
    __shared__ unsigned redrow[BM], redcol[BN];

    const int tid  = threadIdx.x;
    const int wid  = tid >> 5;
    const int lane = tid & 31;
    const int wm   = (wid & 3) * 32;   // warp M offset in tile
    const int wn   = (wid >> 2) * 64;  // warp N offset in tile
    const int mrow0 = mb * BM;
    const int nrow0 = nb * BN;

    if (tid < 128) { redrow[tid] = encf(-2.0f); redcol[tid] = encf(-2.0f); }

    const uint32_t sb = smem_u32(dsm);

    // ---- stage loader: A 128x32, B 128x32 (SW128-swizzled, 16B segments) ----
    auto stage_load = [&](int buf, int k0) {
        uint32_t As = sb + buf * STAGE_BYTES;
        uint32_t Bs = As + 16384;
        #pragma unroll
        for (int i = 0; i < 4; i++) {
            int idx = tid + i * NTH;           // 0..1023
            int r = idx >> 3, c4 = idx & 7;
            cp16(As + swz(r * 128 + c4 * 16),
                 g_xn + (size_t)(mrow0 + r) * D + k0 + c4 * 4);
            cp16(Bs + swz(r * 128 + c4 * 16),
                 g_xn + (size_t)(nrow0 + r) * D + k0 + c4 * 4);
        }
    };

    float acc[2][8][4];
    #pragma unroll
    for (int mt = 0; mt < 2; mt++)
        #pragma unroll
        for (int nt = 0; nt < 8; nt++)
            #pragma unroll
            for (int q = 0; q < 4; q++) acc[mt][nt][q] = 0.0f;

    // ldmatrix lane -> matrix mapping (constant per thread)
    const int amat = lane >> 3;
    const int arow_off = (amat & 1) * 8 + (lane & 7);  // row offset within m16
    const int ac4sel   = amat >> 1;                    // k-half select
    const int bmat = lane >> 3;
    const int brow_off = (bmat >> 1) * 8 + (lane & 7); // n offset within n16
    const int bc4sel   = bmat & 1;
    const int l7 = lane & 7;

    stage_load(0, 0);
    CP_COMMIT();

    #pragma unroll 1
    for (int s = 0; s < NSTAGE; s++) {
        if (s + 1 < NSTAGE) { stage_load((s + 1) & 1, (s + 1) * BK); CP_COMMIT(); CP_WAIT(1); }
        else                { CP_WAIT(0); }
        __syncthreads();

        const uint32_t As = sb + (s & 1) * STAGE_BYTES;
        const uint32_t Bs = As + 16384;

        #pragma unroll
        for (int kk = 0; kk < 4; kk++) {        // 4 x k8 steps
            const int kc4 = kk * 2;
            uint32_t a[2][4];
            #pragma unroll
            for (int mt = 0; mt < 2; mt++) {
                int row = wm + mt * 16 + arow_off;
                uint32_t ad = As + row * 128 + (((kc4 + ac4sel) ^ l7) << 4);
                LDSM_X4(a[mt][0], a[mt][1], a[mt][2], a[mt][3], ad);
            }
            uint32_t b[8][2];
            #pragma unroll
            for (int np = 0; np < 4; np++) {    // n16 blocks
                int row = wn + np * 16 + brow_off;
                uint32_t bd = Bs + row * 128 + (((kc4 + bc4sel) ^ l7) << 4);
                LDSM_X4(b[2 * np][0], b[2 * np][1], b[2 * np + 1][0], b[2 * np + 1][1], bd);
            }
            #pragma unroll
            for (int mt = 0; mt < 2; mt++)
                #pragma unroll
                for (int nt = 0; nt < 8; nt++)
                    MMA_TF32(acc[mt][nt], a[mt], b[nt]);
        }
        __syncthreads();
    }

    // ---- fused epilogue ----
    const int r0 = lane >> 2;
    const int c0 = (lane & 3) * 2;

    // row maxes
    #pragma unroll
    for (int mt = 0; mt < 2; mt++)
        #pragma unroll
        for (int rh = 0; rh < 2; rh++) {
            const int lrow = wm + mt * 16 + rh * 8 + r0;
            const int gi = mrow0 + lrow;
            float rm = -2.0f;
            #pragma unroll
            for (int nt = 0; nt < 8; nt++)
                #pragma unroll
                for (int bq = 0; bq < 2; bq++) {
                    int gj = nrow0 + wn + nt * 8 + c0 + bq;
                    float v = acc[mt][nt][rh * 2 + bq];
                    rm = fmaxf(rm, (gi == gj) ? -2.0f : v);
                }
            rm = fmaxf(rm, __shfl_xor_sync(0xFFFFFFFFu, rm, 1));
            rm = fmaxf(rm, __shfl_xor_sync(0xFFFFFFFFu, rm, 2));
            if ((lane & 3) == 0) atomicMax(&redrow[lrow], encf(rm));
        }

    // col maxes (symmetry: become row maxes of mirror tile)
    #pragma unroll
    for (int nt = 0; nt < 8; nt++)
        #pragma unroll
        for (int bq = 0; bq < 2; bq++) {
            const int lcol = wn + nt * 8 + c0 + bq;
            const int gj = nrow0 + lcol;
            float cm = -2.0f;
            #pragma unroll
            for (int mt = 0; mt < 2; mt++)
                #pragma unroll
                for (int rh = 0; rh < 2; rh++) {
                    int gi = mrow0 + wm + mt * 16 + rh * 8 + r0;
                    float v = acc[mt][nt][rh * 2 + bq];
                    cm = fmaxf(cm, (gi == gj) ? -2.0f : v);
                }
            cm = fmaxf(cm, __shfl_xor_sync(0xFFFFFFFFu, cm, 4));
            cm = fmaxf(cm, __shfl_xor_sync(0xFFFFFFFFu, cm, 8));
            cm = fmaxf(cm, __shfl_xor_sync(0xFFFFFFFFu, cm, 16));
            if (lane < 4) atomicMax(&redcol[lcol], encf(cm));
        }

    __syncthreads();
    if (tid < 128) {
        atomicMax(&g_rmax[mrow0 + tid], redrow[tid]);
        atomicMax(&g_rmax[nrow0 + tid], redcol[tid]);
    }
}

// ---------------------------------------------------------------------------
// Kernel 3: finalize (deterministic reduction).
// ---------------------------------------------------------------------------
__global__ void k_finalize(float* __restrict__ out) {
    __shared__ float sred[256];
    const int tid = threadIdx.x;
    float s = 0.0f;
    for (int i = tid; i < N; i += 256) {
        float smax = decf(g_rmax[i]);
        float d2 = fmaxf(2.0f - 2.0f * smax, 1e-30f);
        s += fmaxf(0.1f, rsqrtf(d2));
    }
    sred[tid] = s;
    __syncthreads();
    #pragma unroll
    for (int o = 128; o; o >>= 1) {
        if (tid < o) sred[tid] += sred[tid + o];
        __syncthreads();
    }
    if (tid == 0) out[0] = sred[0] / (float)N;
}

extern "C" void kernel_launch(void* const* d_in, const int* in_sizes, int n_in,
                              void* d_out, int out_size) {
    const float* x = (const float*)d_in[0];
    float* out = (float*)d_out;

    cudaFuncSetAttribute(k_gemm_max, cudaFuncAttributeMaxDynamicSharedMemorySize, SMEM_DYN);

    k_normalize<<<(N * 32) / 256, 256>>>(x);
    dim3 grid(N / BN, N / BM);   // 64 x 64, upper triangle live
    k_gemm_max<<<grid, NTH, SMEM_DYN>>>();
    k_finalize<<<1, 256>>>(out);
}

// round 7
// speedup vs baseline: 6.6114x; 1.4948x over previous
#include <cuda_runtime.h>
#include <cuda_fp16.h>
#include <cstdint>

// x[8192,256] fp32 -> loss = mean_i 1/sqrt(max(2 - 2*max_{j!=i} s_ij, 1e-30))
// s = Xn Xn^T via mma.sync m16n8k16 fp16 (f32 accum), fused row/col max.
// Triangular 1D grid (2080 live tiles). S never materialized.

#define N 8192
#define D 256
#define BM 128
#define BN 128
#define BK 64                     // K elems per stage (fp16: 128 B per row)
#define NTH 256
#define NSTAGE (D / BK)           // 4
#define STAGE_BYTES 32768         // A 16KB + B 16KB
#define SMEM_DYN (2 * STAGE_BYTES)
#define NBK (N / BN)              // 64
#define NTILES (NBK * (NBK + 1) / 2)   // 2080

__device__ __half  g_xn[N * D];    // fp16 normalized rows
__device__ unsigned g_rmax[N];

__device__ __forceinline__ unsigned encf(float f) {
    unsigned u = __float_as_uint(f);
    return (u & 0x80000000u) ? ~u : (u | 0x80000000u);
}
__device__ __forceinline__ float decf(unsigned u) {
    return (u & 0x80000000u) ? __uint_as_float(u & 0x7fffffffu) : __uint_as_float(~u);
}

__device__ __forceinline__ uint32_t smem_u32(const void* p) {
    uint32_t a;
    asm("{ .reg .u64 t; cvta.to.shared.u64 t, %1; cvt.u32.u64 %0, t; }" : "=r"(a) : "l"(p));
    return a;
}
__device__ __forceinline__ uint32_t swz(uint32_t off) { return off ^ ((off >> 3) & 0x70); }

__device__ __forceinline__ void cp16(uint32_t dst, const void* src) {
    asm volatile("cp.async.cg.shared.global [%0], [%1], 16;" :: "r"(dst), "l"(src) : "memory");
}
#define CP_COMMIT()  asm volatile("cp.async.commit_group;" ::: "memory")
#define CP_WAIT(n)   asm volatile("cp.async.wait_group %0;" :: "n"(n) : "memory")

#define LDSM_X4(R0, R1, R2, R3, ADDR) \
    asm volatile("ldmatrix.sync.aligned.m8n8.x4.shared.b16 {%0,%1,%2,%3}, [%4];" \
        : "=r"(R0), "=r"(R1), "=r"(R2), "=r"(R3) : "r"(ADDR))

#define MMA_F16(d, a, b) \
    asm volatile("mma.sync.aligned.m16n8k16.row.col.f32.f16.f16.f32 " \
        "{%0,%1,%2,%3}, {%4,%5,%6,%7}, {%8,%9}, {%0,%1,%2,%3};" \
        : "+f"((d)[0]), "+f"((d)[1]), "+f"((d)[2]), "+f"((d)[3]) \
        : "r"((a)[0]), "r"((a)[1]), "r"((a)[2]), "r"((a)[3]), \
          "r"((b)[0]), "r"((b)[1]))

// ---------------------------------------------------------------------------
// Kernel 1: row L2-normalize -> fp16, init g_rmax.
// ---------------------------------------------------------------------------
__global__ void k_normalize(const float* __restrict__ x) {
    int gtid = blockIdx.x * blockDim.x + threadIdx.x;
    int row = gtid >> 5;
    int lane = threadIdx.x & 31;
    if (row < N) {
        const float4* xr = reinterpret_cast<const float4*>(x + (size_t)row * D);
        float4 v0 = xr[lane], v1 = xr[lane + 32];
        float ss = v0.x * v0.x + v0.y * v0.y + v0.z * v0.z + v0.w * v0.w +
                   v1.x * v1.x + v1.y * v1.y + v1.z * v1.z + v1.w * v1.w;
        #pragma unroll
        for (int o = 16; o; o >>= 1) ss += __shfl_xor_sync(0xFFFFFFFFu, ss, o);
        float inv = rsqrtf(ss);
        __half2 h[4];
        h[0] = __floats2half2_rn(v0.x * inv, v0.y * inv);
        h[1] = __floats2half2_rn(v0.z * inv, v0.w * inv);
        h[2] = __floats2half2_rn(v1.x * inv, v1.y * inv);
        h[3] = __floats2half2_rn(v1.z * inv, v1.w * inv);
        // lane covers elems [lane*4, lane*4+4) and [128+lane*4, 128+lane*4+4)
        __half2* xo = reinterpret_cast<__half2*>(g_xn + (size_t)row * D);
        xo[lane * 2]          = h[0];
        xo[lane * 2 + 1]      = h[1];
        xo[64 + lane * 2]     = h[2];
        xo[64 + lane * 2 + 1] = h[3];
    }
    if (gtid < N) g_rmax[gtid] = encf(-2.0f);
}

// ---------------------------------------------------------------------------
// Kernel 2: 128x128 tile of S via mma.sync fp16, fused row/col max.
// Triangular 1D grid: tile t -> (mb, nb) with mb <= nb.
// ---------------------------------------------------------------------------
__global__ __launch_bounds__(NTH, 2)
void k_gemm_max() {
    // unrank triangular index
    const int t = blockIdx.x;
    int mb = (int)((2.0f * NBK + 1.0f - sqrtf((2.0f * NBK + 1.0f) * (2.0f * NBK + 1.0f)
                                              - 8.0f * (float)t)) * 0.5f);
    while (mb * NBK - (mb * (mb - 1)) / 2 > t) mb--;
    while ((mb + 1) * NBK - ((mb + 1) * mb) / 2 <= t) mb++;
    const int nb = mb + (t - (mb * NBK - (mb * (mb - 1)) / 2));

    extern __shared__ char dsm[];
    __shared__ unsigned redrow[BM], redcol[BN];

    const int tid  = threadIdx.x;
    const int wid  = tid >> 5;
    const int lane = tid & 31;
    const int wm   = (wid & 3) * 32;   // warp M offset
    const int wn   = (wid >> 2) * 64;  // warp N offset
    const int mrow0 = mb * BM;
    const int nrow0 = nb * BN;

    if (tid < 128) { redrow[tid] = encf(-2.0f); redcol[tid] = encf(-2.0f); }

    const uint32_t sb = smem_u32(dsm);

    // stage loader: A 128x64 fp16 (16KB), B 128x64 fp16 (16KB); 16B = 8 halves
    auto stage_load = [&](int buf, int k0) {
        uint32_t As = sb + buf * STAGE_BYTES;
        uint32_t Bs = As + 16384;
        #pragma unroll
        for (int i = 0; i < 4; i++) {
            int idx = tid + i * NTH;            // 0..1023
            int r = idx >> 3, c8 = idx & 7;     // row, 16B segment
            cp16(As + swz(r * 128 + c8 * 16),
                 g_xn + (size_t)(mrow0 + r) * D + k0 + c8 * 8);
            cp16(Bs + swz(r * 128 + c8 * 16),
                 g_xn + (size_t)(nrow0 + r) * D + k0 + c8 * 8);
        }
    };

    float acc[2][8][4];
    #pragma unroll
    for (int mt = 0; mt < 2; mt++)
        #pragma unroll
        for (int nt = 0; nt < 8; nt++)
            #pragma unroll
            for (int q = 0; q < 4; q++) acc[mt][nt][q] = 0.0f;

    // ldmatrix lane mapping: matrix = lane>>3; rows within m16/n16 = (mat&1)*8 + (lane&7)
    const int mat  = lane >> 3;
    const int rofs = (mat & 1) * 8 + (lane & 7);
    const int ksel = mat >> 1;            // k-segment (8 halves) select
    const int l7   = lane & 7;

    stage_load(0, 0);
    CP_COMMIT();

    #pragma unroll 1
    for (int s = 0; s < NSTAGE; s++) {
        if (s + 1 < NSTAGE) { stage_load((s + 1) & 1, (s + 1) * BK); CP_COMMIT(); CP_WAIT(1); }
        else                { CP_WAIT(0); }
        __syncthreads();

        const uint32_t As = sb + (s & 1) * STAGE_BYTES;
        const uint32_t Bs = As + 16384;

        #pragma unroll
        for (int kk = 0; kk < 4; kk++) {       // 4 x k16 steps
            uint32_t a[2][4];
            #pragma unroll
            for (int mt = 0; mt < 2; mt++) {
                int row = wm + mt * 16 + rofs;
                uint32_t ad = As + row * 128 + (((kk * 2 + ksel) ^ l7) << 4);
                LDSM_X4(a[mt][0], a[mt][1], a[mt][2], a[mt][3], ad);
            }
            uint32_t b[8][2];
            #pragma unroll
            for (int np = 0; np < 4; np++) {   // n16 blocks
                int row = wn + np * 16 + rofs;
                uint32_t bd = Bs + row * 128 + (((kk * 2 + ksel) ^ l7) << 4);
                uint32_t r0, r1, r2, r3;
                LDSM_X4(r0, r1, r2, r3, bd);
                b[2 * np][0] = r0; b[2 * np][1] = r2;         // n0-7: k lo, k hi
                b[2 * np + 1][0] = r1; b[2 * np + 1][1] = r3; // n8-15
            }
            #pragma unroll
            for (int mt = 0; mt < 2; mt++)
                #pragma unroll
                for (int nt = 0; nt < 8; nt++)
                    MMA_F16(acc[mt][nt], a[mt], b[nt]);
        }
        __syncthreads();
    }

    // ---- fused epilogue (acc frag: r = l>>2 + rh*8, c = (l&3)*2 + bq) ----
    const int r0 = lane >> 2;
    const int c0 = (lane & 3) * 2;

    #pragma unroll
    for (int mt = 0; mt < 2; mt++)
        #pragma unroll
        for (int rh = 0; rh < 2; rh++) {
            const int lrow = wm + mt * 16 + rh * 8 + r0;
            const int gi = mrow0 + lrow;
            float rm = -2.0f;
            #pragma unroll
            for (int nt = 0; nt < 8; nt++)
                #pragma unroll
                for (int bq = 0; bq < 2; bq++) {
                    int gj = nrow0 + wn + nt * 8 + c0 + bq;
                    float v = acc[mt][nt][rh * 2 + bq];
                    rm = fmaxf(rm, (gi == gj) ? -2.0f : v);
                }
            rm = fmaxf(rm, __shfl_xor_sync(0xFFFFFFFFu, rm, 1));
            rm = fmaxf(rm, __shfl_xor_sync(0xFFFFFFFFu, rm, 2));
            if ((lane & 3) == 0) atomicMax(&redrow[lrow], encf(rm));
        }

    #pragma unroll
    for (int nt = 0; nt < 8; nt++)
        #pragma unroll
        for (int bq = 0; bq < 2; bq++) {
            const int lcol = wn + nt * 8 + c0 + bq;
            const int gj = nrow0 + lcol;
            float cm = -2.0f;
            #pragma unroll
            for (int mt = 0; mt < 2; mt++)
                #pragma unroll
                for (int rh = 0; rh < 2; rh++) {
                    int gi = mrow0 + wm + mt * 16 + rh * 8 + r0;
                    float v = acc[mt][nt][rh * 2 + bq];
                    cm = fmaxf(cm, (gi == gj) ? -2.0f : v);
                }
            cm = fmaxf(cm, __shfl_xor_sync(0xFFFFFFFFu, cm, 4));
            cm = fmaxf(cm, __shfl_xor_sync(0xFFFFFFFFu, cm, 8));
            cm = fmaxf(cm, __shfl_xor_sync(0xFFFFFFFFu, cm, 16));
            if (lane < 4) atomicMax(&redcol[lcol], encf(cm));
        }

    __syncthreads();
    if (tid < 128) {
        atomicMax(&g_rmax[mrow0 + tid], redrow[tid]);
        atomicMax(&g_rmax[nrow0 + tid], redcol[tid]);
    }
}

// ---------------------------------------------------------------------------
// Kernel 3: finalize (deterministic reduction).
// ---------------------------------------------------------------------------
__global__ void k_finalize(float* __restrict__ out) {
    __shared__ float sred[256];
    const int tid = threadIdx.x;
    float s = 0.0f;
    for (int i = tid; i < N; i += 256) {
        float smax = decf(g_rmax[i]);
        float d2 = fmaxf(2.0f - 2.0f * smax, 1e-30f);
        s += fmaxf(0.1f, rsqrtf(d2));
    }
    sred[tid] = s;
    __syncthreads();
    #pragma unroll
    for (int o = 128; o; o >>= 1) {
        if (tid < o) sred[tid] += sred[tid + o];
        __syncthreads();
    }
    if (tid == 0) out[0] = sred[0] / (float)N;
}

extern "C" void kernel_launch(void* const* d_in, const int* in_sizes, int n_in,
                              void* d_out, int out_size) {
    const float* x = (const float*)d_in[0];
    float* out = (float*)d_out;

    cudaFuncSetAttribute(k_gemm_max, cudaFuncAttributeMaxDynamicSharedMemorySize, SMEM_DYN);

    k_normalize<<<(N * 32) / 256, 256>>>(x);
    k_gemm_max<<<NTILES, NTH, SMEM_DYN>>>();
    k_finalize<<<1, 256>>>(out);
}